// round 3
// baseline (speedup 1.0000x reference)
#include <cuda_runtime.h>
#include <math.h>

// Problem constants
#define BB   8192      // batch
#define TT   20        // seq len
#define FF   812       // nfeatures
#define HH   400       // hidden
#define GG   1600      // 4*HID
#define LDW  813       // W_ih leading dim (NF+1)
#define VARI 811       // imputed feature index

// GEMM tiling
#define BM 64
#define BN 64
#define BK 16
#define PAD 4

// ---------------- device scratch (static; no runtime allocation) ----------------
__device__ float g_gates_pre[(size_t)BB * TT * GG];  // [b*T+t][1600]  (~1.05 GB)
__device__ float g_gates[(size_t)BB * GG];           // per-step gates (52 MB)
__device__ float g_h[(size_t)BB * HH];
__device__ float g_c[(size_t)BB * HH];
__device__ float g_xvar[BB];
__device__ float g_num[TT];
__device__ float g_den[TT];
__device__ float g_wsum[HH];
__device__ float g_w811[GG];   // W_ih[:, 811]
__device__ float g_w812[GG];   // W_ih[:, 812] (mask column)
__device__ float g_bias[GG];   // b_ih + b_hh

// ---------------- small setup kernels ----------------
__global__ void init_kernel() {
    size_t i = (size_t)blockIdx.x * blockDim.x + threadIdx.x;
    size_t n = (size_t)BB * HH;
    if (i < n) { g_h[i] = 0.f; g_c[i] = 0.f; }
    if (i < TT) g_num[i] = 0.f;
}

__global__ void prep_kernel(const float* __restrict__ W_ih,
                            const float* __restrict__ b_ih,
                            const float* __restrict__ b_hh) {
    int n = blockIdx.x * blockDim.x + threadIdx.x;
    if (n < GG) {
        g_w811[n] = W_ih[(size_t)n * LDW + VARI];
        g_w812[n] = W_ih[(size_t)n * LDW + FF];
        g_bias[n] = b_ih[n] + b_hh[n];
    }
}

__global__ void wsum_kernel(const float* __restrict__ W_decay) {
    int j = blockIdx.x;               // 0..HH-1
    int tid = threadIdx.x;            // 128
    float s = 0.f;
    for (int f = tid; f < FF; f += 128) s += W_decay[(size_t)j * FF + f];
    __shared__ float red[128];
    red[tid] = s; __syncthreads();
    for (int st = 64; st > 0; st >>= 1) {
        if (tid < st) red[tid] += red[tid + st];
        __syncthreads();
    }
    if (tid == 0) g_wsum[j] = red[0];
}

__global__ void den_kernel(const float* __restrict__ masks) {
    int t = blockIdx.x;               // 0..TT-1
    int tid = threadIdx.x;            // 256
    float s = 0.f;
    for (int b = tid; b < BB; b += 256) s += masks[(size_t)b * TT + t];
    __shared__ float red[256];
    red[tid] = s; __syncthreads();
    for (int st = 128; st > 0; st >>= 1) {
        if (tid < st) red[tid] += red[tid + st];
        __syncthreads();
    }
    if (tid == 0) g_den[t] = red[0];
}

// ---------------- precompute GEMM: gates_pre = values @ W_ih[:, :812]^T + folds ----------------
// A: values [M=BB*TT, FF] row-major (row r = b*TT + t). W: W_ih [GG, LDW].
// Epilogue: + m[r]*w812[n] + bias[n] - values[r,811]*w811[n]  (excludes VAR column from the sum)
__global__ __launch_bounds__(256)
void gemm_pre_kernel(const float* __restrict__ A,
                     const float* __restrict__ W,
                     const float* __restrict__ masks) {
    __shared__ float As[BK][BM + PAD];
    __shared__ float Bs[BK][BN + PAD];
    const int tid = threadIdx.x;
    const int tx = tid & 15, ty = tid >> 4;
    const int row0 = blockIdx.y * BM;
    const int col0 = blockIdx.x * BN;
    float acc[4][4] = {};

    for (int k0 = 0; k0 < FF; k0 += BK) {
        #pragma unroll
        for (int i = 0; i < 4; i++) {
            int idx = tid + i * 256;
            int m = idx >> 4, k = idx & 15;
            int gk = k0 + k;
            As[k][m] = (gk < FF) ? A[(size_t)(row0 + m) * FF + gk] : 0.f;
        }
        #pragma unroll
        for (int i = 0; i < 4; i++) {
            int idx = tid + i * 256;
            int n = idx >> 4, k = idx & 15;
            int gk = k0 + k;
            Bs[k][n] = (gk < FF) ? W[(size_t)(col0 + n) * LDW + gk] : 0.f;
        }
        __syncthreads();
        #pragma unroll
        for (int k = 0; k < BK; k++) {
            float a[4], b[4];
            #pragma unroll
            for (int i = 0; i < 4; i++) a[i] = As[k][ty * 4 + i];
            #pragma unroll
            for (int j = 0; j < 4; j++) b[j] = Bs[k][tx * 4 + j];
            #pragma unroll
            for (int i = 0; i < 4; i++)
                #pragma unroll
                for (int j = 0; j < 4; j++)
                    acc[i][j] += a[i] * b[j];
        }
        __syncthreads();
    }

    #pragma unroll
    for (int i = 0; i < 4; i++) {
        int r = row0 + ty * 4 + i;
        float mk = masks[r];
        float v811 = A[(size_t)r * FF + VARI];
        #pragma unroll
        for (int j = 0; j < 4; j++) {
            int n = col0 + tx * 4 + j;
            g_gates_pre[(size_t)r * GG + n] =
                acc[i][j] + mk * g_w812[n] + g_bias[n] - v811 * g_w811[n];
        }
    }
}

// ---------------- per-step decay + imputation + loss numerator ----------------
__global__ void decay_kernel(const float* __restrict__ deltas,
                             const float* __restrict__ masks,
                             const float* __restrict__ values,
                             const float* __restrict__ b_decay,
                             const float* __restrict__ W_reg,
                             const float* __restrict__ b_reg,
                             float* __restrict__ imp, int write_loss, int t) {
    int b = blockIdx.x;
    int tid = threadIdx.x;  // 128
    float d = deltas[(size_t)b * TT + t];
    float m = masks[(size_t)b * TT + t];
    float local = 0.f;
    for (int j = tid; j < HH; j += 128) {
        float a = d * g_wsum[j] + b_decay[j];
        float gamma = expf(-fmaxf(a, 0.f));
        float hv = g_h[(size_t)b * HH + j] * gamma;
        g_h[(size_t)b * HH + j] = hv;
        local += hv * W_reg[j];
    }
    __shared__ float red[128];
    red[tid] = local; __syncthreads();
    for (int s = 64; s > 0; s >>= 1) {
        if (tid < s) red[tid] += red[tid + s];
        __syncthreads();
    }
    if (tid == 0) {
        float xh = red[0] + b_reg[0];
        float xval = values[((size_t)b * TT + t) * FF + VARI];
        float xv = xval * m + (1.f - m) * xh;
        g_xvar[b] = xv;
        imp[(size_t)b * TT + t] = xv;
        if (write_loss) atomicAdd(&g_num[t], fabsf(xv - xh) * m);
    }
}

// ---------------- per-step GEMM: gates = gates_pre[t] + xvar*w811 + h @ W_hh^T ----------------
__global__ __launch_bounds__(256)
void gemm_hh_kernel(const float* __restrict__ Whh, int t) {
    __shared__ float As[BK][BM + PAD];
    __shared__ float Bs[BK][BN + PAD];
    const int tid = threadIdx.x;
    const int tx = tid & 15, ty = tid >> 4;
    const int row0 = blockIdx.y * BM;   // batch
    const int col0 = blockIdx.x * BN;   // gate index
    float acc[4][4] = {};

    for (int k0 = 0; k0 < HH; k0 += BK) {   // 400 % 16 == 0, no guards
        #pragma unroll
        for (int i = 0; i < 4; i++) {
            int idx = tid + i * 256;
            int m = idx >> 4, k = idx & 15;
            As[k][m] = g_h[(size_t)(row0 + m) * HH + (k0 + k)];
        }
        #pragma unroll
        for (int i = 0; i < 4; i++) {
            int idx = tid + i * 256;
            int n = idx >> 4, k = idx & 15;
            Bs[k][n] = Whh[(size_t)(col0 + n) * HH + (k0 + k)];
        }
        __syncthreads();
        #pragma unroll
        for (int k = 0; k < BK; k++) {
            float a[4], b[4];
            #pragma unroll
            for (int i = 0; i < 4; i++) a[i] = As[k][ty * 4 + i];
            #pragma unroll
            for (int j = 0; j < 4; j++) b[j] = Bs[k][tx * 4 + j];
            #pragma unroll
            for (int i = 0; i < 4; i++)
                #pragma unroll
                for (int j = 0; j < 4; j++)
                    acc[i][j] += a[i] * b[j];
        }
        __syncthreads();
    }

    #pragma unroll
    for (int i = 0; i < 4; i++) {
        int r = row0 + ty * 4 + i;
        float xv = g_xvar[r];
        size_t prer = ((size_t)r * TT + t) * GG;
        #pragma unroll
        for (int j = 0; j < 4; j++) {
            int n = col0 + tx * 4 + j;
            g_gates[(size_t)r * GG + n] = acc[i][j] + g_gates_pre[prer + n] + xv * g_w811[n];
        }
    }
}

// ---------------- per-step LSTM pointwise update ----------------
__global__ void lstm_kernel() {
    size_t idx = (size_t)blockIdx.x * blockDim.x + threadIdx.x;  // BB*HH
    if (idx >= (size_t)BB * HH) return;
    size_t b = idx / HH;
    int j = (int)(idx % HH);
    const float* g = &g_gates[b * GG];
    float ig = g[j], fg = g[j + HH], gg = g[j + 2 * HH], og = g[j + 3 * HH];
    float c = g_c[idx];
    float si = 1.f / (1.f + expf(-ig));
    float sf = 1.f / (1.f + expf(-fg));
    float so = 1.f / (1.f + expf(-og));
    float tg = tanhf(gg);
    c = sf * c + si * tg;
    g_c[idx] = c;
    g_h[idx] = so * tanhf(c);
}

__global__ void loss_kernel(float* __restrict__ out) {
    if (threadIdx.x == 0 && blockIdx.x == 0) {
        float s = 0.f;
        for (int t = 0; t < TT; t++) s += g_num[t] / (g_den[t] + 1e-5f);
        out[0] = s / (float)TT;
    }
}

// ---------------- launch ----------------
extern "C" void kernel_launch(void* const* d_in, const int* in_sizes, int n_in,
                              void* d_out, int out_size) {
    const float* values  = (const float*)d_in[0];
    const float* masks   = (const float*)d_in[1];
    const float* deltas  = (const float*)d_in[2];
    const float* W_decay = (const float*)d_in[3];
    const float* b_decay = (const float*)d_in[4];
    const float* W_reg   = (const float*)d_in[5];
    const float* b_reg   = (const float*)d_in[6];
    const float* W_ih    = (const float*)d_in[7];
    const float* W_hh    = (const float*)d_in[8];
    const float* b_ih    = (const float*)d_in[9];
    const float* b_hh    = (const float*)d_in[10];
    float* out = (float*)d_out;

    // Output layout: [loss, imputations(B,T)] flattened. If out_size == B*T,
    // the harness only keeps imputations; handle both.
    int has_loss = (out_size > BB * TT) ? 1 : 0;
    float* imp = out + has_loss;

    size_t nInit = (size_t)BB * HH;
    init_kernel<<<(unsigned)((nInit + 255) / 256), 256>>>();
    prep_kernel<<<(GG + 255) / 256, 256>>>(W_ih, b_ih, b_hh);
    wsum_kernel<<<HH, 128>>>(W_decay);
    if (has_loss) den_kernel<<<TT, 256>>>(masks);

    dim3 gpre(GG / BN, (BB * TT) / BM);   // 25 x 2560
    gemm_pre_kernel<<<gpre, 256>>>(values, W_ih, masks);

    dim3 ghh(GG / BN, BB / BM);           // 25 x 128
    unsigned lstmGrid = (unsigned)(((size_t)BB * HH + 255) / 256);
    for (int t = 0; t < TT; t++) {
        decay_kernel<<<BB, 128>>>(deltas, masks, values, b_decay, W_reg, b_reg,
                                  imp, has_loss, t);
        gemm_hh_kernel<<<ghh, 256>>>(W_hh, t);
        lstm_kernel<<<lstmGrid, 256>>>();
    }
    if (has_loss) loss_kernel<<<1, 32>>>(out);
}

// round 4
// speedup vs baseline: 1.2400x; 1.2400x over previous
#include <cuda_runtime.h>
#include <math.h>

// Problem constants
#define BB   8192      // batch
#define TT   20        // seq len
#define FF   812       // nfeatures
#define HH   400       // hidden
#define GG   1600      // 4*HID
#define LDW  813       // W_ih leading dim (NF+1)
#define VARI 811       // imputed feature index
#define M1   (BB * TT) // rows of precompute GEMM

// GEMM tiling: 128x128x16, 256 threads, 8x8 microtile, double-buffered smem
#define BM 128
#define BN 128
#define BK 16

// ---------------- device scratch (static; no runtime allocation) ----------------
__device__ float g_gates_pre[(size_t)M1 * GG];   // ~1.05 GB
__device__ float g_gates[(size_t)BB * GG];       // per-step gates (52 MB)
__device__ float g_h[(size_t)BB * HH];
__device__ float g_c[(size_t)BB * HH];
__device__ float g_xvar[BB];
__device__ float g_num[TT];
__device__ float g_den[TT];
__device__ float g_wsum[HH];
__device__ float g_w811[GG];   // W_ih[:, 811]
__device__ float g_w812[GG];   // W_ih[:, 812] (mask column)
__device__ float g_bias[GG];   // b_ih + b_hh

// ---------------- small setup kernels ----------------
__global__ void init_kernel() {
    size_t i = (size_t)blockIdx.x * blockDim.x + threadIdx.x;
    size_t n = (size_t)BB * HH;
    if (i < n) { g_h[i] = 0.f; g_c[i] = 0.f; }
    if (i < TT) g_num[i] = 0.f;
}

__global__ void prep_kernel(const float* __restrict__ W_ih,
                            const float* __restrict__ b_ih,
                            const float* __restrict__ b_hh) {
    int n = blockIdx.x * blockDim.x + threadIdx.x;
    if (n < GG) {
        g_w811[n] = W_ih[(size_t)n * LDW + VARI];
        g_w812[n] = W_ih[(size_t)n * LDW + FF];
        g_bias[n] = b_ih[n] + b_hh[n];
    }
}

__global__ void wsum_kernel(const float* __restrict__ W_decay) {
    int j = blockIdx.x;
    int tid = threadIdx.x;            // 128
    float s = 0.f;
    for (int f = tid; f < FF; f += 128) s += W_decay[(size_t)j * FF + f];
    __shared__ float red[128];
    red[tid] = s; __syncthreads();
    for (int st = 64; st > 0; st >>= 1) {
        if (tid < st) red[tid] += red[tid + st];
        __syncthreads();
    }
    if (tid == 0) g_wsum[j] = red[0];
}

__global__ void den_kernel(const float* __restrict__ masks) {
    int t = blockIdx.x;
    int tid = threadIdx.x;            // 256
    float s = 0.f;
    for (int b = tid; b < BB; b += 256) s += masks[(size_t)b * TT + t];
    __shared__ float red[256];
    red[tid] = s; __syncthreads();
    for (int st = 128; st > 0; st >>= 1) {
        if (tid < st) red[tid] += red[tid + st];
        __syncthreads();
    }
    if (tid == 0) g_den[t] = red[0];
}

// =====================================================================
// Precompute GEMM: gates_pre[r][n] = sum_k values[r][k]*W_ih[n][k] (k<812)
//                  + m[r]*w812[n] + bias[n] - values[r][811]*w811[n]
// 128x128x16 double-buffered, 256 threads, 8x8 microtile.
// A rows 16B-aligned (stride 812 floats); W_ih stride 813 -> scalar loads.
// =====================================================================
__global__ __launch_bounds__(256, 2)
void gemm_pre_kernel(const float* __restrict__ A,
                     const float* __restrict__ W,
                     const float* __restrict__ masks) {
    __shared__ float As[2][BK][BM];
    __shared__ float Bs[2][BK][BN];

    const int tid = threadIdx.x;
    const int tx = tid & 15, ty = tid >> 4;
    const int row0 = blockIdx.y * BM;
    const int col0 = blockIdx.x * BN;

    // A-load mapping: ar in 0..63 (+64), ac = float4 index in k
    const int ar = tid >> 2, ac = tid & 3;
    // B-load mapping: bn in 0..127, bk = 0 or 8
    const int bn = tid >> 1, bk = (tid & 1) * 8;
    const bool bn_ok = (col0 + bn) < GG;

    const int NS = (FF + BK - 1) / BK;   // 51 stages

    float4 a0, a1;
    float bv[8];

    // ---- prologue: load stage 0 ----
    {
        int kk = ac * 4;
        if (kk + 3 < FF) {
            a0 = *(const float4*)&A[(size_t)(row0 + ar) * FF + kk];
            a1 = *(const float4*)&A[(size_t)(row0 + ar + 64) * FF + kk];
        } else { a0 = make_float4(0,0,0,0); a1 = a0; }
        #pragma unroll
        for (int i = 0; i < 8; i++) {
            int k = bk + i;
            bv[i] = (bn_ok && k < FF) ? W[(size_t)(col0 + bn) * LDW + k] : 0.f;
        }
        As[0][ac*4+0][ar] = a0.x; As[0][ac*4+1][ar] = a0.y;
        As[0][ac*4+2][ar] = a0.z; As[0][ac*4+3][ar] = a0.w;
        As[0][ac*4+0][ar+64] = a1.x; As[0][ac*4+1][ar+64] = a1.y;
        As[0][ac*4+2][ar+64] = a1.z; As[0][ac*4+3][ar+64] = a1.w;
        #pragma unroll
        for (int i = 0; i < 8; i++) Bs[0][bk + i][bn] = bv[i];
    }
    __syncthreads();

    float acc[8][8] = {};
    int buf = 0;

    for (int s = 0; s < NS; s++) {
        // prefetch next stage into registers
        if (s + 1 < NS) {
            int k0 = (s + 1) * BK;
            int kk = k0 + ac * 4;
            if (kk + 3 < FF) {
                a0 = *(const float4*)&A[(size_t)(row0 + ar) * FF + kk];
                a1 = *(const float4*)&A[(size_t)(row0 + ar + 64) * FF + kk];
            } else { a0 = make_float4(0,0,0,0); a1 = a0; }
            #pragma unroll
            for (int i = 0; i < 8; i++) {
                int k = k0 + bk + i;
                bv[i] = (bn_ok && k < FF) ? W[(size_t)(col0 + bn) * LDW + k] : 0.f;
            }
        }
        // compute current stage
        #pragma unroll
        for (int k = 0; k < BK; k++) {
            float4 af0 = *(float4*)&As[buf][k][ty * 4];
            float4 af1 = *(float4*)&As[buf][k][ty * 4 + 64];
            float4 bf0 = *(float4*)&Bs[buf][k][tx * 4];
            float4 bf1 = *(float4*)&Bs[buf][k][tx * 4 + 64];
            float a[8] = {af0.x, af0.y, af0.z, af0.w, af1.x, af1.y, af1.z, af1.w};
            float b[8] = {bf0.x, bf0.y, bf0.z, bf0.w, bf1.x, bf1.y, bf1.z, bf1.w};
            #pragma unroll
            for (int i = 0; i < 8; i++)
                #pragma unroll
                for (int j = 0; j < 8; j++)
                    acc[i][j] += a[i] * b[j];
        }
        if (s + 1 < NS) {
            int nb = buf ^ 1;
            As[nb][ac*4+0][ar] = a0.x; As[nb][ac*4+1][ar] = a0.y;
            As[nb][ac*4+2][ar] = a0.z; As[nb][ac*4+3][ar] = a0.w;
            As[nb][ac*4+0][ar+64] = a1.x; As[nb][ac*4+1][ar+64] = a1.y;
            As[nb][ac*4+2][ar+64] = a1.z; As[nb][ac*4+3][ar+64] = a1.w;
            #pragma unroll
            for (int i = 0; i < 8; i++) Bs[nb][bk + i][bn] = bv[i];
            __syncthreads();
            buf = nb;
        }
    }

    // epilogue
    #pragma unroll
    for (int i = 0; i < 8; i++) {
        int r = row0 + ty * 4 + (i < 4 ? i : 60 + i);
        float mk = masks[r];
        float v811 = A[(size_t)r * FF + VARI];
        #pragma unroll
        for (int j = 0; j < 8; j++) {
            int n = col0 + tx * 4 + (j < 4 ? j : 60 + j);
            if (n < GG)
                g_gates_pre[(size_t)r * GG + n] =
                    acc[i][j] + mk * g_w812[n] + g_bias[n] - v811 * g_w811[n];
        }
    }
}

// =====================================================================
// Per-step GEMM: gates[b][n] = sum_k h[b][k]*W_hh[n][k]
//                + gates_pre[b*T+t][n] + xvar[b]*w811[n]
// Same 128x128x16 structure; both operands 16B-aligned (stride 400 floats).
// =====================================================================
__global__ __launch_bounds__(256, 2)
void gemm_hh_kernel(const float* __restrict__ Whh, int t) {
    __shared__ float As[2][BK][BM];
    __shared__ float Bs[2][BK][BN];

    const int tid = threadIdx.x;
    const int tx = tid & 15, ty = tid >> 4;
    const int row0 = blockIdx.y * BM;   // batch
    const int col0 = blockIdx.x * BN;   // gate index

    const int ar = tid >> 2, ac = tid & 3;
    const int br = tid >> 2, bc = tid & 3;
    const bool b0_ok = (col0 + br) < GG;
    const bool b1_ok = (col0 + br + 64) < GG;

    const int NS = HH / BK;   // 25 stages, K=400 exact

    float4 a0, a1, w0, w1;
    const float4 Z = make_float4(0,0,0,0);

    {
        int kk = ac * 4;
        a0 = *(const float4*)&g_h[(size_t)(row0 + ar) * HH + kk];
        a1 = *(const float4*)&g_h[(size_t)(row0 + ar + 64) * HH + kk];
        int wk = bc * 4;
        w0 = b0_ok ? *(const float4*)&Whh[(size_t)(col0 + br) * HH + wk] : Z;
        w1 = b1_ok ? *(const float4*)&Whh[(size_t)(col0 + br + 64) * HH + wk] : Z;
        As[0][ac*4+0][ar] = a0.x; As[0][ac*4+1][ar] = a0.y;
        As[0][ac*4+2][ar] = a0.z; As[0][ac*4+3][ar] = a0.w;
        As[0][ac*4+0][ar+64] = a1.x; As[0][ac*4+1][ar+64] = a1.y;
        As[0][ac*4+2][ar+64] = a1.z; As[0][ac*4+3][ar+64] = a1.w;
        Bs[0][bc*4+0][br] = w0.x; Bs[0][bc*4+1][br] = w0.y;
        Bs[0][bc*4+2][br] = w0.z; Bs[0][bc*4+3][br] = w0.w;
        Bs[0][bc*4+0][br+64] = w1.x; Bs[0][bc*4+1][br+64] = w1.y;
        Bs[0][bc*4+2][br+64] = w1.z; Bs[0][bc*4+3][br+64] = w1.w;
    }
    __syncthreads();

    float acc[8][8] = {};
    int buf = 0;

    for (int s = 0; s < NS; s++) {
        if (s + 1 < NS) {
            int k0 = (s + 1) * BK;
            int kk = k0 + ac * 4;
            a0 = *(const float4*)&g_h[(size_t)(row0 + ar) * HH + kk];
            a1 = *(const float4*)&g_h[(size_t)(row0 + ar + 64) * HH + kk];
            int wk = k0 + bc * 4;
            w0 = b0_ok ? *(const float4*)&Whh[(size_t)(col0 + br) * HH + wk] : Z;
            w1 = b1_ok ? *(const float4*)&Whh[(size_t)(col0 + br + 64) * HH + wk] : Z;
        }
        #pragma unroll
        for (int k = 0; k < BK; k++) {
            float4 af0 = *(float4*)&As[buf][k][ty * 4];
            float4 af1 = *(float4*)&As[buf][k][ty * 4 + 64];
            float4 bf0 = *(float4*)&Bs[buf][k][tx * 4];
            float4 bf1 = *(float4*)&Bs[buf][k][tx * 4 + 64];
            float a[8] = {af0.x, af0.y, af0.z, af0.w, af1.x, af1.y, af1.z, af1.w};
            float b[8] = {bf0.x, bf0.y, bf0.z, bf0.w, bf1.x, bf1.y, bf1.z, bf1.w};
            #pragma unroll
            for (int i = 0; i < 8; i++)
                #pragma unroll
                for (int j = 0; j < 8; j++)
                    acc[i][j] += a[i] * b[j];
        }
        if (s + 1 < NS) {
            int nb = buf ^ 1;
            As[nb][ac*4+0][ar] = a0.x; As[nb][ac*4+1][ar] = a0.y;
            As[nb][ac*4+2][ar] = a0.z; As[nb][ac*4+3][ar] = a0.w;
            As[nb][ac*4+0][ar+64] = a1.x; As[nb][ac*4+1][ar+64] = a1.y;
            As[nb][ac*4+2][ar+64] = a1.z; As[nb][ac*4+3][ar+64] = a1.w;
            Bs[nb][bc*4+0][br] = w0.x; Bs[nb][bc*4+1][br] = w0.y;
            Bs[nb][bc*4+2][br] = w0.z; Bs[nb][bc*4+3][br] = w0.w;
            Bs[nb][bc*4+0][br+64] = w1.x; Bs[nb][bc*4+1][br+64] = w1.y;
            Bs[nb][bc*4+2][br+64] = w1.z; Bs[nb][bc*4+3][br+64] = w1.w;
            __syncthreads();
            buf = nb;
        }
    }

    #pragma unroll
    for (int i = 0; i < 8; i++) {
        int r = row0 + ty * 4 + (i < 4 ? i : 60 + i);
        float xv = g_xvar[r];
        size_t prer = ((size_t)r * TT + t) * GG;
        #pragma unroll
        for (int j = 0; j < 8; j++) {
            int n = col0 + tx * 4 + (j < 4 ? j : 60 + j);
            if (n < GG)
                g_gates[(size_t)r * GG + n] = acc[i][j] + g_gates_pre[prer + n] + xv * g_w811[n];
        }
    }
}

// ---------------- per-step decay + imputation + loss numerator ----------------
__global__ void decay_kernel(const float* __restrict__ deltas,
                             const float* __restrict__ masks,
                             const float* __restrict__ values,
                             const float* __restrict__ b_decay,
                             const float* __restrict__ W_reg,
                             const float* __restrict__ b_reg,
                             float* __restrict__ imp, int write_loss, int t) {
    int b = blockIdx.x;
    int tid = threadIdx.x;  // 128
    float d = deltas[(size_t)b * TT + t];
    float m = masks[(size_t)b * TT + t];
    float local = 0.f;
    for (int j = tid; j < HH; j += 128) {
        float a = d * g_wsum[j] + b_decay[j];
        float gamma = expf(-fmaxf(a, 0.f));
        float hv = g_h[(size_t)b * HH + j] * gamma;
        g_h[(size_t)b * HH + j] = hv;
        local += hv * W_reg[j];
    }
    __shared__ float red[128];
    red[tid] = local; __syncthreads();
    for (int s = 64; s > 0; s >>= 1) {
        if (tid < s) red[tid] += red[tid + s];
        __syncthreads();
    }
    if (tid == 0) {
        float xh = red[0] + b_reg[0];
        float xval = values[((size_t)b * TT + t) * FF + VARI];
        float xv = xval * m + (1.f - m) * xh;
        g_xvar[b] = xv;
        imp[(size_t)b * TT + t] = xv;
        if (write_loss) atomicAdd(&g_num[t], fabsf(xv - xh) * m);
    }
}

// ---------------- per-step LSTM pointwise update ----------------
__global__ void lstm_kernel() {
    size_t idx = (size_t)blockIdx.x * blockDim.x + threadIdx.x;  // BB*HH
    if (idx >= (size_t)BB * HH) return;
    size_t b = idx / HH;
    int j = (int)(idx % HH);
    const float* g = &g_gates[b * GG];
    float ig = g[j], fg = g[j + HH], gg = g[j + 2 * HH], og = g[j + 3 * HH];
    float c = g_c[idx];
    float si = 1.f / (1.f + expf(-ig));
    float sf = 1.f / (1.f + expf(-fg));
    float so = 1.f / (1.f + expf(-og));
    float tg = tanhf(gg);
    c = sf * c + si * tg;
    g_c[idx] = c;
    g_h[idx] = so * tanhf(c);
}

__global__ void loss_kernel(float* __restrict__ out) {
    if (threadIdx.x == 0 && blockIdx.x == 0) {
        float s = 0.f;
        for (int t = 0; t < TT; t++) s += g_num[t] / (g_den[t] + 1e-5f);
        out[0] = s / (float)TT;
    }
}

// ---------------- launch ----------------
extern "C" void kernel_launch(void* const* d_in, const int* in_sizes, int n_in,
                              void* d_out, int out_size) {
    const float* values  = (const float*)d_in[0];
    const float* masks   = (const float*)d_in[1];
    const float* deltas  = (const float*)d_in[2];
    const float* W_decay = (const float*)d_in[3];
    const float* b_decay = (const float*)d_in[4];
    const float* W_reg   = (const float*)d_in[5];
    const float* b_reg   = (const float*)d_in[6];
    const float* W_ih    = (const float*)d_in[7];
    const float* W_hh    = (const float*)d_in[8];
    const float* b_ih    = (const float*)d_in[9];
    const float* b_hh    = (const float*)d_in[10];
    float* out = (float*)d_out;

    int has_loss = (out_size > BB * TT) ? 1 : 0;
    float* imp = out + has_loss;

    size_t nInit = (size_t)BB * HH;
    init_kernel<<<(unsigned)((nInit + 255) / 256), 256>>>();
    prep_kernel<<<(GG + 255) / 256, 256>>>(W_ih, b_ih, b_hh);
    wsum_kernel<<<HH, 128>>>(W_decay);
    if (has_loss) den_kernel<<<TT, 256>>>(masks);

    dim3 gpre((GG + BN - 1) / BN, M1 / BM);     // 13 x 1280
    gemm_pre_kernel<<<gpre, 256>>>(values, W_ih, masks);

    dim3 ghh((GG + BN - 1) / BN, BB / BM);      // 13 x 64
    unsigned lstmGrid = (unsigned)(((size_t)BB * HH + 255) / 256);
    for (int t = 0; t < TT; t++) {
        decay_kernel<<<BB, 128>>>(deltas, masks, values, b_decay, W_reg, b_reg,
                                  imp, has_loss, t);
        gemm_hh_kernel<<<ghh, 256>>>(W_hh, t);
        lstm_kernel<<<lstmGrid, 256>>>();
    }
    if (has_loss) loss_kernel<<<1, 32>>>(out);
}

// round 5
// speedup vs baseline: 1.5059x; 1.2144x over previous
#include <cuda_runtime.h>
#include <cuda_bf16.h>
#include <mma.h>
#include <math.h>

using namespace nvcuda;

// Problem constants
#define BB   8192
#define TT   20
#define FF   812
#define HH   400
#define GG   1600
#define LDW  813       // W_ih leading dim (NF+1)
#define VARI 811
#define M1   (BB * TT)

// Tiling
#define BM 128
#define BN 128
#define LDA 24         // smem ld in elements: 16 k + 8 pad (multiple of 8)

// ---------------- device scratch ----------------
__device__ float g_gates_pre[(size_t)M1 * GG];   // ~1.05 GB
__device__ float g_gates[(size_t)BB * GG];
__device__ float g_h[(size_t)BB * HH];
__device__ float g_c[(size_t)BB * HH];
__device__ float g_xvar[BB];
__device__ float g_num[TT];
__device__ float g_den[TT];
__device__ float g_wsum[HH];
__device__ float g_w811[GG];   // W_ih[:, 811]
__device__ float g_bias[GG];   // b_ih + b_hh

// ---------------- small setup kernels ----------------
__global__ void init_kernel() {
    size_t i = (size_t)blockIdx.x * blockDim.x + threadIdx.x;
    size_t n = (size_t)BB * HH;
    if (i < n) { g_h[i] = 0.f; g_c[i] = 0.f; }
    if (i < TT) g_num[i] = 0.f;
}

__global__ void prep_kernel(const float* __restrict__ W_ih,
                            const float* __restrict__ b_ih,
                            const float* __restrict__ b_hh) {
    int n = blockIdx.x * blockDim.x + threadIdx.x;
    if (n < GG) {
        g_w811[n] = W_ih[(size_t)n * LDW + VARI];
        g_bias[n] = b_ih[n] + b_hh[n];
    }
}

__global__ void wsum_kernel(const float* __restrict__ W_decay) {
    int j = blockIdx.x;
    int tid = threadIdx.x;  // 128
    float s = 0.f;
    for (int f = tid; f < FF; f += 128) s += W_decay[(size_t)j * FF + f];
    __shared__ float red[128];
    red[tid] = s; __syncthreads();
    for (int st = 64; st > 0; st >>= 1) {
        if (tid < st) red[tid] += red[tid + st];
        __syncthreads();
    }
    if (tid == 0) g_wsum[j] = red[0];
}

__global__ void den_kernel(const float* __restrict__ masks) {
    int t = blockIdx.x;
    int tid = threadIdx.x;  // 256
    float s = 0.f;
    for (int b = tid; b < BB; b += 256) s += masks[(size_t)b * TT + t];
    __shared__ float red[256];
    red[tid] = s; __syncthreads();
    for (int st = 128; st > 0; st >>= 1) {
        if (tid < st) red[tid] += red[tid + st];
        __syncthreads();
    }
    if (tid == 0) g_den[t] = red[0];
}

// ---------------- wmma helpers ----------------
typedef wmma::fragment<wmma::matrix_a, 16, 16, 16, __nv_bfloat16, wmma::row_major> FragA;
typedef wmma::fragment<wmma::matrix_b, 16, 16, 16, __nv_bfloat16, wmma::col_major> FragB;
typedef wmma::fragment<wmma::accumulator, 16, 16, 16, float> FragC;

__device__ __forceinline__ void cvt_split(float v, __nv_bfloat16& h, __nv_bfloat16& l) {
    h = __float2bfloat16(v);
    l = __float2bfloat16(v - __bfloat162float(h));
}

// One K=16 chunk: acc += Ah*Bh + Ah*Bl + Al*Bh  (bf16 split GEMM)
__device__ __forceinline__ void mma_chunk(
    const __nv_bfloat16* __restrict__ Ah, const __nv_bfloat16* __restrict__ Al,
    const __nv_bfloat16* __restrict__ Bh, const __nv_bfloat16* __restrict__ Bl,
    int wm, int wn, FragC acc[4][2])
{
    FragB bh[2], bl[2];
    #pragma unroll
    for (int j = 0; j < 2; j++) {
        wmma::load_matrix_sync(bh[j], Bh + (wn * 32 + j * 16) * LDA, LDA);
        wmma::load_matrix_sync(bl[j], Bl + (wn * 32 + j * 16) * LDA, LDA);
    }
    #pragma unroll
    for (int i = 0; i < 4; i++) {
        FragA ah, al;
        wmma::load_matrix_sync(ah, Ah + (wm * 64 + i * 16) * LDA, LDA);
        wmma::load_matrix_sync(al, Al + (wm * 64 + i * 16) * LDA, LDA);
        #pragma unroll
        for (int j = 0; j < 2; j++) {
            wmma::mma_sync(acc[i][j], ah, bh[j], acc[i][j]);
            wmma::mma_sync(acc[i][j], ah, bl[j], acc[i][j]);
            wmma::mma_sync(acc[i][j], al, bh[j], acc[i][j]);
        }
    }
}

// =====================================================================
// Precompute GEMM (tensor cores, bf16 split, epilogue folded as K-ext):
//   K layout: k in [0,811) -> values (col 811 zeroed)
//             k == 811     -> 0         (x B col 811; excluded term)
//             k == 812     -> mask      (x W_ih natural mask column)
//             k == 813     -> 1.0       (x (b_ih + b_hh))
//   gates_pre[r][n] = result, stored directly via wmma.
// =====================================================================
#define NCH_PRE 51   // ceil(814/16)

__global__ __launch_bounds__(256, 2)
void gemm_pre_kernel(const float* __restrict__ A,
                     const float* __restrict__ W,
                     const float* __restrict__ masks) {
    __shared__ __nv_bfloat16 Ah[BM * LDA], Al[BM * LDA];
    __shared__ __nv_bfloat16 Bh[BN * LDA], Bl[BN * LDA];

    const int tid = threadIdx.x;
    const int wid = tid >> 5;
    const int wm = wid & 1, wn = wid >> 1;
    const int row0 = blockIdx.y * BM;
    const int col0 = blockIdx.x * BN;

    const int lr = tid >> 1;          // 0..127
    const int lk = (tid & 1) * 8;     // 0 or 8
    const size_t abase = (size_t)(row0 + lr) * FF;
    const float mk = masks[row0 + lr];
    const int ng = col0 + lr;
    const bool nok = ng < GG;
    const size_t wbase = (size_t)(nok ? ng : 0) * LDW;
    const float bias = nok ? g_bias[ng] : 0.f;

    FragC acc[4][2];
    #pragma unroll
    for (int i = 0; i < 4; i++)
        #pragma unroll
        for (int j = 0; j < 2; j++)
            wmma::fill_fragment(acc[i][j], 0.f);

    for (int ch = 0; ch < NCH_PRE; ch++) {
        const int kc = ch * 16;
        float va[8], vb[8];
        if (ch < 50) {
            float4 p = *(const float4*)&A[abase + kc + lk];
            float4 q = *(const float4*)&A[abase + kc + lk + 4];
            va[0] = p.x; va[1] = p.y; va[2] = p.z; va[3] = p.w;
            va[4] = q.x; va[5] = q.y; va[6] = q.z; va[7] = q.w;
            #pragma unroll
            for (int i = 0; i < 8; i++)
                vb[i] = nok ? W[wbase + kc + lk + i] : 0.f;
        } else {
            #pragma unroll
            for (int i = 0; i < 8; i++) {
                int gk = kc + lk + i;   // 800..815
                va[i] = (gk < VARI) ? A[abase + gk]
                       : (gk == FF ? mk : (gk == 813 ? 1.f : 0.f));
                vb[i] = (!nok) ? 0.f
                       : (gk < LDW ? W[wbase + gk] : (gk == 813 ? bias : 0.f));
            }
        }
        __syncthreads();
        #pragma unroll
        for (int i = 0; i < 8; i++) {
            cvt_split(va[i], Ah[lr * LDA + lk + i], Al[lr * LDA + lk + i]);
            cvt_split(vb[i], Bh[lr * LDA + lk + i], Bl[lr * LDA + lk + i]);
        }
        __syncthreads();
        mma_chunk(Ah, Al, Bh, Bl, wm, wn, acc);
    }

    #pragma unroll
    for (int i = 0; i < 4; i++) {
        int r = row0 + wm * 64 + i * 16;
        #pragma unroll
        for (int j = 0; j < 2; j++) {
            int cf = col0 + wn * 32 + j * 16;
            if (cf < GG)
                wmma::store_matrix_sync(&g_gates_pre[(size_t)r * GG + cf],
                                        acc[i][j], GG, wmma::mem_row_major);
        }
    }
}

// =====================================================================
// Per-step GEMM (tensor cores):
//   acc <- gates_pre[b*T+t] tile   (load_matrix_sync, ldm = T*G)
//   K in [0,400): h @ W_hh^T;  k == 400: xvar[b] * w811[n]
//   gates = result, stored via wmma.
// =====================================================================
#define NCH_HH 26   // 25 full + 1 extension chunk

__global__ __launch_bounds__(256, 2)
void gemm_hh_kernel(const float* __restrict__ Whh, int t) {
    __shared__ __nv_bfloat16 Ah[BM * LDA], Al[BM * LDA];
    __shared__ __nv_bfloat16 Bh[BN * LDA], Bl[BN * LDA];

    const int tid = threadIdx.x;
    const int wid = tid >> 5;
    const int wm = wid & 1, wn = wid >> 1;
    const int row0 = blockIdx.y * BM;    // batch
    const int col0 = blockIdx.x * BN;    // gate index

    const int lr = tid >> 1;
    const int lk = (tid & 1) * 8;
    const size_t hbase = (size_t)(row0 + lr) * HH;
    const float xv = g_xvar[row0 + lr];
    const int ng = col0 + lr;
    const bool nok = ng < GG;
    const size_t wbase = (size_t)(nok ? ng : 0) * HH;
    const float w811v = nok ? g_w811[ng] : 0.f;

    FragC acc[4][2];
    #pragma unroll
    for (int i = 0; i < 4; i++) {
        int r = row0 + wm * 64 + i * 16;
        #pragma unroll
        for (int j = 0; j < 2; j++) {
            int cf = col0 + wn * 32 + j * 16;
            if (cf < GG)
                wmma::load_matrix_sync(acc[i][j],
                    &g_gates_pre[((size_t)r * TT + t) * GG + cf],
                    (unsigned)(TT * GG), wmma::mem_row_major);
            else
                wmma::fill_fragment(acc[i][j], 0.f);
        }
    }

    for (int ch = 0; ch < NCH_HH; ch++) {
        const int kc = ch * 16;
        float va[8], vb[8];
        if (ch < 25) {
            float4 p = *(const float4*)&g_h[hbase + kc + lk];
            float4 q = *(const float4*)&g_h[hbase + kc + lk + 4];
            va[0] = p.x; va[1] = p.y; va[2] = p.z; va[3] = p.w;
            va[4] = q.x; va[5] = q.y; va[6] = q.z; va[7] = q.w;
            if (nok) {
                float4 u = *(const float4*)&Whh[wbase + kc + lk];
                float4 v = *(const float4*)&Whh[wbase + kc + lk + 4];
                vb[0] = u.x; vb[1] = u.y; vb[2] = u.z; vb[3] = u.w;
                vb[4] = v.x; vb[5] = v.y; vb[6] = v.z; vb[7] = v.w;
            } else {
                #pragma unroll
                for (int i = 0; i < 8; i++) vb[i] = 0.f;
            }
        } else {
            #pragma unroll
            for (int i = 0; i < 8; i++) {
                bool is400 = (lk + i) == 0;   // kc==400
                va[i] = is400 ? xv : 0.f;
                vb[i] = is400 ? w811v : 0.f;
            }
        }
        __syncthreads();
        #pragma unroll
        for (int i = 0; i < 8; i++) {
            cvt_split(va[i], Ah[lr * LDA + lk + i], Al[lr * LDA + lk + i]);
            cvt_split(vb[i], Bh[lr * LDA + lk + i], Bl[lr * LDA + lk + i]);
        }
        __syncthreads();
        mma_chunk(Ah, Al, Bh, Bl, wm, wn, acc);
    }

    #pragma unroll
    for (int i = 0; i < 4; i++) {
        int r = row0 + wm * 64 + i * 16;
        #pragma unroll
        for (int j = 0; j < 2; j++) {
            int cf = col0 + wn * 32 + j * 16;
            if (cf < GG)
                wmma::store_matrix_sync(&g_gates[(size_t)r * GG + cf],
                                        acc[i][j], GG, wmma::mem_row_major);
        }
    }
}

// ---------------- per-step decay + imputation + loss numerator ----------------
__global__ void decay_kernel(const float* __restrict__ deltas,
                             const float* __restrict__ masks,
                             const float* __restrict__ values,
                             const float* __restrict__ b_decay,
                             const float* __restrict__ W_reg,
                             const float* __restrict__ b_reg,
                             float* __restrict__ imp, int write_loss, int t) {
    int b = blockIdx.x;
    int tid = threadIdx.x;  // 128
    float d = deltas[(size_t)b * TT + t];
    float m = masks[(size_t)b * TT + t];
    float local = 0.f;
    for (int j = tid; j < HH; j += 128) {
        float a = d * g_wsum[j] + b_decay[j];
        float gamma = expf(-fmaxf(a, 0.f));
        float hv = g_h[(size_t)b * HH + j] * gamma;
        g_h[(size_t)b * HH + j] = hv;
        local += hv * W_reg[j];
    }
    __shared__ float red[128];
    red[tid] = local; __syncthreads();
    for (int s = 64; s > 0; s >>= 1) {
        if (tid < s) red[tid] += red[tid + s];
        __syncthreads();
    }
    if (tid == 0) {
        float xh = red[0] + b_reg[0];
        float xval = values[((size_t)b * TT + t) * FF + VARI];
        float xv = xval * m + (1.f - m) * xh;
        g_xvar[b] = xv;
        imp[(size_t)b * TT + t] = xv;
        if (write_loss) atomicAdd(&g_num[t], fabsf(xv - xh) * m);
    }
}

// ---------------- per-step LSTM pointwise update ----------------
__global__ void lstm_kernel() {
    size_t idx = (size_t)blockIdx.x * blockDim.x + threadIdx.x;  // BB*HH
    if (idx >= (size_t)BB * HH) return;
    size_t b = idx / HH;
    int j = (int)(idx % HH);
    const float* g = &g_gates[b * GG];
    float ig = g[j], fg = g[j + HH], gg = g[j + 2 * HH], og = g[j + 3 * HH];
    float c = g_c[idx];
    float si = 1.f / (1.f + expf(-ig));
    float sf = 1.f / (1.f + expf(-fg));
    float so = 1.f / (1.f + expf(-og));
    float tg = tanhf(gg);
    c = sf * c + si * tg;
    g_c[idx] = c;
    g_h[idx] = so * tanhf(c);
}

__global__ void loss_kernel(float* __restrict__ out) {
    if (threadIdx.x == 0 && blockIdx.x == 0) {
        float s = 0.f;
        for (int t = 0; t < TT; t++) s += g_num[t] / (g_den[t] + 1e-5f);
        out[0] = s / (float)TT;
    }
}

// ---------------- launch ----------------
extern "C" void kernel_launch(void* const* d_in, const int* in_sizes, int n_in,
                              void* d_out, int out_size) {
    const float* values  = (const float*)d_in[0];
    const float* masks   = (const float*)d_in[1];
    const float* deltas  = (const float*)d_in[2];
    const float* W_decay = (const float*)d_in[3];
    const float* b_decay = (const float*)d_in[4];
    const float* W_reg   = (const float*)d_in[5];
    const float* b_reg   = (const float*)d_in[6];
    const float* W_ih    = (const float*)d_in[7];
    const float* W_hh    = (const float*)d_in[8];
    const float* b_ih    = (const float*)d_in[9];
    const float* b_hh    = (const float*)d_in[10];
    float* out = (float*)d_out;

    int has_loss = (out_size > BB * TT) ? 1 : 0;
    float* imp = out + has_loss;

    size_t nInit = (size_t)BB * HH;
    init_kernel<<<(unsigned)((nInit + 255) / 256), 256>>>();
    prep_kernel<<<(GG + 255) / 256, 256>>>(W_ih, b_ih, b_hh);
    wsum_kernel<<<HH, 128>>>(W_decay);
    if (has_loss) den_kernel<<<TT, 256>>>(masks);

    dim3 gpre((GG + BN - 1) / BN, M1 / BM);     // 13 x 1280
    gemm_pre_kernel<<<gpre, 256>>>(values, W_ih, masks);

    dim3 ghh((GG + BN - 1) / BN, BB / BM);      // 13 x 64
    unsigned lstmGrid = (unsigned)(((size_t)BB * HH + 255) / 256);
    for (int t = 0; t < TT; t++) {
        decay_kernel<<<BB, 128>>>(deltas, masks, values, b_decay, W_reg, b_reg,
                                  imp, has_loss, t);
        gemm_hh_kernel<<<ghh, 256>>>(W_hh, t);
        lstm_kernel<<<lstmGrid, 256>>>();
    }
    if (has_loss) loss_kernel<<<1, 32>>>(out);
}